// round 14
// baseline (speedup 1.0000x reference)
#include <cuda_runtime.h>
#include <cuda_fp16.h>
#include <cstdint>

// NCC loss, 9x9 box, SAME zero pad, n=81 (matches reference conv).
// Round 14: factored horizontal taps on the R13 champion (53.8us).
//   box9 = 3-sum of 3-sums:
//     pass1: X[u] = {P=(a,c), PP=(aa,cc), PQ=(af,cf), GQ=(ff,f)}  (uint4/col)
//     pass2: T[u] = X[u] + X[u+1] + X[u+2]
//     taps:  A = T[x] + T[x+3] + T[x+6]   -> 3 LDS.128 + 8 HADD2 per pixel
//   (was 9 taps x (LDS.64 + PRMT + 4 HFMA2) = 54/px; now ~34/px incl passes)
// Same fp16 product/sum regime as R13 -> same error class (~2e-6).
// Chassis unchanged: depth-4 cp.async, wait_group 2, uniform commit,
// __launch_bounds__(128,6), fp16 ring + fp32 S exact-cancel slide, merged
// epilogue, deterministic fused reduction. 3 barriers/stage.

#define WW 512
#define HH 512
#define NB 32
#define COLS 128
#define STRIPH 64
#define NBLK (4 * 8 * 32)   // 1024 blocks
#define NSTAGE 24           // 72 row-steps / 3 rows per stage
#define VECS_PER_STAGE 306  // 9 row-images * 34 float4
#define UNITS 408           // 3 rows * 136 cols per stage

__device__ float        g_partials[NBLK];
__device__ unsigned int g_count = 0;

__device__ __forceinline__ void cp16(uint32_t dst, const float* src, bool ok) {
    asm volatile("cp.async.cg.shared.global [%0], [%1], 16, %2;"
                 :: "r"(dst), "l"(src), "r"(ok ? 16 : 0) : "memory");
}
__device__ __forceinline__ void cp_commit() {
    asm volatile("cp.async.commit_group;" ::: "memory");
}
__device__ __forceinline__ void cp_wait2() {
    asm volatile("cp.async.wait_group 2;" ::: "memory");
}
__device__ __forceinline__ __half2 h2u(unsigned v) {
    return *reinterpret_cast<__half2*>(&v);
}
__device__ __forceinline__ unsigned u2h(__half2 h) {
    return *reinterpret_cast<unsigned*>(&h);
}

__global__ __launch_bounds__(128, 6)
void ncc_fused(const float* __restrict__ img1,
               const float* __restrict__ img2,
               const float* __restrict__ fus,
               float* __restrict__ out)
{
    const int tid   = threadIdx.x;
    const int xbase = blockIdx.x * COLS;
    const int ybase = blockIdx.y * STRIPH;
    const int b     = blockIdx.z;

    const size_t base = (size_t)b * (size_t)(HH * WW);
    const float* p1 = img1 + base;
    const float* p2 = img2 + base;
    const float* pf = fus  + base;

    // staged fp32: [buf][img*3+row][136]; img-major so flat u / u+408 / u+816
    __shared__ float rows[4][9][136];
    // product fields and 3-sums for the CURRENT stage (flat u = row*136 + x)
    __shared__ __align__(16) uint4 X[UNITS + 4];   // +4 pad for u+2 overrun
    __shared__ __align__(16) uint4 T[UNITS];
    __shared__ float red[4];
    __shared__ int   lastflag;

    const uint32_t smem_rows = (uint32_t)__cvta_generic_to_shared(&rows[0][0][0]);

    // ---- loop-invariant staging descriptors (3 vecs per thread) ----
    const float* pb[3];
    int          joff[3];
    uint32_t     doff[3];
    bool         cokv[3];
    bool         act[3];
#pragma unroll
    for (int it = 0; it < 3; ++it) {
        const int i  = tid + 128 * it;
        act[it]      = (i < VECS_PER_STAGE);
        const int ii  = act[it] ? i : 0;
        const int ri  = ii / 34;            // row-image 0..8 = img*3 + jj
        const int vec = ii - ri * 34;
        const int img = ri / 3;
        joff[it]      = ri - img * 3;
        const int gx  = xbase - 4 + vec * 4;
        const bool ck = (gx >= 0) && (gx <= WW - 4);
        cokv[it]      = ck;
        const float* p = (img == 0) ? p1 : ((img == 1) ? p2 : pf);
        pb[it]        = p + (ck ? gx : 0);
        doff[it]      = (uint32_t)((ri * 136 + vec * 4) * 4);
    }

    auto stage = [&](int s, int buf) {
        const int r0 = ybase - 4 + 3 * s;
        const uint32_t bb = smem_rows + (uint32_t)(buf * (9 * 136 * 4));
#pragma unroll
        for (int it = 0; it < 3; ++it) {
            if (act[it]) {
                const int  r   = r0 + joff[it];
                const bool rok = ((unsigned)r < (unsigned)HH);
                const int  rc  = rok ? r : 0;
                cp16(bb + doff[it], pb[it] + (size_t)rc * WW, rok && cokv[it]);
            }
        }
    };

    // ring stores A1..A4 (4 half2 per slot = 36 regs); S fp32
    __half2 ring[9][4];
    float S[8];
#pragma unroll
    for (int j = 0; j < 9; ++j)
#pragma unroll
        for (int q = 0; q < 4; ++q) ring[j][q] = __floats2half2_rn(0.0f, 0.0f);
#pragma unroll
    for (int q = 0; q < 8; ++q) S[q] = 0.0f;

    float acc = 0.0f;
    const float inv_n = 1.0f / 81.0f;

    stage(0, 0); cp_commit();
    stage(1, 1); cp_commit();
    stage(2, 2); cp_commit();

    for (int a = 0; a < 8; ++a) {
#pragma unroll
        for (int g = 0; g < 3; ++g) {
            const int s   = 3 * a + g;
            const int buf = s & 3;
            // pending groups: s, s+1, s+2 (later ones may be empty commits)
            cp_wait2();
            __syncthreads();   // stage-s fp32 visible; prev iter's T reads done

            if (s + 3 < NSTAGE) stage(s + 3, (s + 3) & 3);
            cp_commit();       // unconditional: uniform group accounting

            // ---- pass 1: fp32 -> packed product fields X ----
            {
                const float* Rf32 = &rows[buf][0][0];
#pragma unroll
                for (int it = 0; it < 4; ++it) {
                    const int u = tid + 128 * it;
                    if (u < UNITS) {
                        const float av = Rf32[u];
                        const float cv = Rf32[u + 408];
                        const float fv = Rf32[u + 816];
                        const __half2 P = __floats2half2_rn(av, cv);
                        const __half2 Q = __floats2half2_rn(fv, fv);
                        const __half2 G = __floats2half2_rn(fv, 1.0f);
                        uint4 x;
                        x.x = u2h(P);
                        x.y = u2h(__hmul2(P, P));   // (aa, cc)
                        x.z = u2h(__hmul2(P, Q));   // (af, cf)
                        x.w = u2h(__hmul2(G, Q));   // (ff, f)
                        X[u] = x;
                    }
                }
            }
            __syncthreads();

            // ---- pass 2: 3-sums  T[u] = X[u] + X[u+1] + X[u+2] ----
            {
#pragma unroll
                for (int it = 0; it < 4; ++it) {
                    const int u = tid + 128 * it;
                    if (u < UNITS) {
                        const uint4 x0 = X[u];
                        const uint4 x1 = X[u + 1];
                        const uint4 x2 = X[u + 2];
                        uint4 t;
                        t.x = u2h(__hadd2(__hadd2(h2u(x0.x), h2u(x1.x)), h2u(x2.x)));
                        t.y = u2h(__hadd2(__hadd2(h2u(x0.y), h2u(x1.y)), h2u(x2.y)));
                        t.z = u2h(__hadd2(__hadd2(h2u(x0.z), h2u(x1.z)), h2u(x2.z)));
                        t.w = u2h(__hadd2(__hadd2(h2u(x0.w), h2u(x1.w)), h2u(x2.w)));
                        T[u] = t;
                    }
                }
            }
            __syncthreads();

#pragma unroll
            for (int j = 0; j < 3; ++j) {
                const int slot = 3 * g + j;     // static 0..8 == (9a+slot) % 9
                const int bse  = j * 136 + tid;

                // ---- 9-tap = 3-sum of T ----
                const uint4 t0 = T[bse];
                const uint4 t1 = T[bse + 3];
                const uint4 t2 = T[bse + 6];
                const __half2 A1 = __hadd2(__hadd2(h2u(t0.x), h2u(t1.x)), h2u(t2.x));
                const __half2 A2 = __hadd2(__hadd2(h2u(t0.y), h2u(t1.y)), h2u(t2.y));
                const __half2 A3 = __hadd2(__hadd2(h2u(t0.z), h2u(t1.z)), h2u(t2.z));
                const __half2 A4 = __hadd2(__hadd2(h2u(t0.w), h2u(t1.w)), h2u(t2.w));

                // ---- dequantize new and retiring entries (identical path) ----
                const float2 u1 = __half22float2(A1);   // (Sa,  Sc)
                const float2 u2 = __half22float2(A2);   // (Saa, Scc)
                const float2 u3 = __half22float2(A3);   // (Saf, Scf)
                const float2 u4 = __half22float2(A4);   // (Sff, Sf)
                const float2 o1 = __half22float2(ring[slot][0]);
                const float2 o2 = __half22float2(ring[slot][1]);
                const float2 o3 = __half22float2(ring[slot][2]);
                const float2 o4 = __half22float2(ring[slot][3]);

                // ---- vertical slide in fp32 (exact cancellation) ----
                S[0] += u1.x - o1.x;  S[3] += u1.y - o1.y;
                S[1] += u2.x - o2.x;  S[4] += u2.y - o2.y;
                S[2] += u3.x - o3.x;  S[5] += u3.y - o3.y;
                S[7] += u4.x - o4.x;  S[6] += u4.y - o4.y;

                ring[slot][0] = A1;
                ring[slot][1] = A2;
                ring[slot][2] = A3;
                ring[slot][3] = A4;

                // ---- emit output row (row-step i = 9a+slot >= 8) ----
                if (a > 0 || slot >= 8) {
                    const float mA = S[0] * inv_n;
                    const float mB = S[3] * inv_n;
                    const float mJ = S[6] * inv_n;
                    const float crossA = fmaf(-mA, S[6], S[2]);
                    const float varA   = fmaf(-mA, S[0], S[1]);
                    const float varJ   = fmaf(-mJ, S[6], S[7]);
                    const float crossB = fmaf(-mB, S[6], S[5]);
                    const float varB   = fmaf(-mB, S[3], S[4]);
                    const float dA = fmaf(varA, varJ, 1e-5f);
                    const float dB = fmaf(varB, varJ, 1e-5f);
                    // ccA + ccB = (crossA^2*dB + crossB^2*dA) / (dA*dB)
                    const float num = fmaf(crossB * crossB, dA,
                                           crossA * crossA * dB);
                    const float rcp = __fdividef(1.0f, dA * dB);
                    acc = fmaf(-num, rcp, acc + 2.0f);   // += 2 - (ccA+ccB)
                }
            }
            // T readers (this iter) vs next pass2 writers: separated by next
            // iter's top+post-pass1 barriers. X readers (pass2) vs next pass1
            // writers: separated by next iter's top barrier.
        }
    }

    // ---- deterministic block reduction ----
#pragma unroll
    for (int off = 16; off > 0; off >>= 1)
        acc += __shfl_xor_sync(0xffffffffu, acc, off);
    if ((tid & 31) == 0) red[tid >> 5] = acc;
    __syncthreads();

    const int bidx = (blockIdx.z * 8 + blockIdx.y) * 4 + blockIdx.x;
    if (tid == 0) {
        g_partials[bidx] = (red[0] + red[1]) + (red[2] + red[3]);
        __threadfence();
        unsigned int old = atomicInc(&g_count, NBLK - 1);  // wraps: graph-replay safe
        lastflag = (old == NBLK - 1);
    }
    __syncthreads();

    if (lastflag) {
        float v = 0.0f;
#pragma unroll
        for (int m = 0; m < NBLK / 128; ++m)
            v += g_partials[tid + 128 * m];
#pragma unroll
        for (int off = 16; off > 0; off >>= 1)
            v += __shfl_xor_sync(0xffffffffu, v, off);
        if ((tid & 31) == 0) red[tid >> 5] = v;
        __syncthreads();
        if (tid == 0) {
            const float tot = (red[0] + red[1]) + (red[2] + red[3]);
            // mean(combined) = sum(2*combined) * 0.5 / 2^23 = tot * 2^-24
            out[0] = tot * 5.9604644775390625e-08f;
        }
    }
}

extern "C" void kernel_launch(void* const* d_in, const int* in_sizes, int n_in,
                              void* d_out, int out_size)
{
    (void)in_sizes; (void)n_in; (void)out_size;
    const float* img1 = (const float*)d_in[0];
    const float* img2 = (const float*)d_in[1];
    const float* fus  = (const float*)d_in[2];

    dim3 grid(4, 8, NB);   // 1024 blocks
    ncc_fused<<<grid, 128>>>(img1, img2, fus, (float*)d_out);
}

// round 15
// speedup vs baseline: 1.3282x; 1.3282x over previous
#include <cuda_runtime.h>
#include <cuda_fp16.h>
#include <cstdint>

// NCC loss, 9x9 box, SAME zero pad, n=81 (matches reference conv).
// Round 15: R13 champion kernel (53.8us) + wave-packed grid.
//   - grid (4,7,32) = 896 blocks vs 888 concurrent slots (148 SM x 6 blocks)
//     -> 1.009 waves (was 1024/888 = 1.153 waves + ragged tail).
//   - uniform 74-row strips; 7th strip overhangs (emit rows guarded to y<512,
//     staged rows clamped + zero-filled by the existing predicates).
//   - 28 stages of 3 rows, iterated 10x3 with an s<28 guard; slot = 3g+j
//     stays compile-time (27a = 0 mod 9).
// Kernel body identical to R13: packed HFMA2 taps on per-stage half2 pairs,
// fp16 ring + fp32 S exact-cancel slide, depth-4 cp.async wait_group 2,
// uniform commit, 2 barriers/stage, merged epilogue, 80-reg / 6-block chassis.
// Deterministic fused reduction (fixed-order, wrapping atomicInc).

#define WW 512
#define HH 512
#define NB 32
#define COLS 128
#define STRIPH 74
#define NYB 7
#define NBLK (4 * NYB * 32)   // 896 blocks
#define NSTAGE 28             // 84 row-steps (74+8 real, 2 pad)
#define VECS_PER_STAGE 306    // 9 row-images * 34 float4
#define UNITS 408             // 3 rows * 136 cols per stage

__device__ float        g_partials[NBLK];
__device__ unsigned int g_count = 0;

__device__ __forceinline__ void cp16(uint32_t dst, const float* src, bool ok) {
    asm volatile("cp.async.cg.shared.global [%0], [%1], 16, %2;"
                 :: "r"(dst), "l"(src), "r"(ok ? 16 : 0) : "memory");
}
__device__ __forceinline__ void cp_commit() {
    asm volatile("cp.async.commit_group;" ::: "memory");
}
__device__ __forceinline__ void cp_wait2() {
    asm volatile("cp.async.wait_group 2;" ::: "memory");
}

__global__ __launch_bounds__(128, 6)
void ncc_fused(const float* __restrict__ img1,
               const float* __restrict__ img2,
               const float* __restrict__ fus,
               float* __restrict__ out)
{
    const int tid   = threadIdx.x;
    const int xbase = blockIdx.x * COLS;
    const int ybase = blockIdx.y * STRIPH;
    const int b     = blockIdx.z;

    const size_t base = (size_t)b * (size_t)(HH * WW);
    const float* p1 = img1 + base;
    const float* p2 = img2 + base;
    const float* pf = fus  + base;

    // staged fp32: [buf][img*3+row][136]
    __shared__ float rows[4][9][136];
    // packed taps for the CURRENT stage: uint2 {P=(a,c), G=(f,1)} per (r,x)
    __shared__ __align__(16) uint2 W[UNITS];
    __shared__ float red[4];
    __shared__ int   lastflag;

    const uint32_t smem_rows = (uint32_t)__cvta_generic_to_shared(&rows[0][0][0]);

    // ---- loop-invariant staging descriptors (3 vecs per thread) ----
    const float* pb[3];
    int          joff[3];
    uint32_t     doff[3];
    bool         cokv[3];
    bool         act[3];
#pragma unroll
    for (int it = 0; it < 3; ++it) {
        const int i  = tid + 128 * it;
        act[it]      = (i < VECS_PER_STAGE);
        const int ii  = act[it] ? i : 0;
        const int ri  = ii / 34;            // row-image 0..8 = img*3 + jj
        const int vec = ii - ri * 34;
        const int img = ri / 3;
        joff[it]      = ri - img * 3;
        const int gx  = xbase - 4 + vec * 4;
        const bool ck = (gx >= 0) && (gx <= WW - 4);
        cokv[it]      = ck;
        const float* p = (img == 0) ? p1 : ((img == 1) ? p2 : pf);
        pb[it]        = p + (ck ? gx : 0);
        doff[it]      = (uint32_t)((ri * 136 + vec * 4) * 4);
    }

    auto stage = [&](int s, int buf) {
        const int r0 = ybase - 4 + 3 * s;
#pragma unroll
        for (int it = 0; it < 3; ++it) {
            if (act[it]) {
                const int  r   = r0 + joff[it];
                const bool rok = ((unsigned)r < (unsigned)HH);
                const int  rc  = rok ? r : 0;
                const uint32_t bb = smem_rows + (uint32_t)(buf * (9 * 136 * 4));
                cp16(bb + doff[it], pb[it] + (size_t)rc * WW, rok && cokv[it]);
            }
        }
    };

    // ring stores A1..A4 (4 half2 per slot = 36 regs); S fp32
    __half2 ring[9][4];
    float S[8];
#pragma unroll
    for (int j = 0; j < 9; ++j)
#pragma unroll
        for (int q = 0; q < 4; ++q) ring[j][q] = __floats2half2_rn(0.0f, 0.0f);
#pragma unroll
    for (int q = 0; q < 8; ++q) S[q] = 0.0f;

    float acc = 0.0f;
    const float inv_n = 1.0f / 81.0f;
    // emit window: 8 <= i < ilim  (i = row-step index; y = ybase + i - 8)
    const int ilim = min(STRIPH + 8, HH + 8 - ybase);

    stage(0, 0); cp_commit();
    stage(1, 1); cp_commit();
    stage(2, 2); cp_commit();

    for (int a = 0; a < 10; ++a) {
#pragma unroll
        for (int g = 0; g < 3; ++g) {
            const int s = 3 * a + g;
            if (s < NSTAGE) {
                const int buf = s & 3;
                // pending groups: s, s+1, s+2 (later ones may be empty commits)
                cp_wait2();
                __syncthreads();   // staged fp32 visible; prev W reads done

                // ---- conversion pass: staged fp32 -> packed W ----
                {
                    const float* Rf32 = &rows[buf][0][0];
#pragma unroll
                    for (int it = 0; it < 4; ++it) {
                        const int u = tid + 128 * it;
                        if (u < UNITS) {
                            const float av = Rf32[u];
                            const float cv = Rf32[u + 408];
                            const float fv = Rf32[u + 816];
                            const __half2 P = __floats2half2_rn(av, cv);
                            const __half2 G = __floats2half2_rn(fv, 1.0f);
                            uint2 pk;
                            pk.x = *reinterpret_cast<const unsigned*>(&P);
                            pk.y = *reinterpret_cast<const unsigned*>(&G);
                            W[u] = pk;
                        }
                    }
                }
                __syncthreads();   // W visible to all

                if (s + 3 < NSTAGE) stage(s + 3, (s + 3) & 3);
                cp_commit();       // unconditional: uniform group accounting

#pragma unroll
                for (int j = 0; j < 3; ++j) {
                    const int slot = 3 * g + j;   // static 0..8 = (9a+3g+j)%9

                    // ---- packed 9-tap horizontal sums ----
                    __half2 A1 = __floats2half2_rn(0.0f, 0.0f);
                    __half2 A2 = A1, A3 = A1, A4 = A1;
#pragma unroll
                    for (int k = 0; k < 9; ++k) {
                        const uint2 pk = W[j * 136 + tid + k];
                        const __half2 P = *reinterpret_cast<const __half2*>(&pk.x);
                        const __half2 G = *reinterpret_cast<const __half2*>(&pk.y);
                        const __half2 Q = __low2half2(G);   // (f,f)
                        A1 = __hadd2(A1, P);                // (Sa,  Sc)
                        A2 = __hfma2(P, P, A2);             // (Saa, Scc)
                        A3 = __hfma2(P, Q, A3);             // (Saf, Scf)
                        A4 = __hfma2(G, Q, A4);             // (Sff, Sf)
                    }

                    // ---- dequantize new and retiring entries ----
                    const float2 u1 = __half22float2(A1);
                    const float2 u2 = __half22float2(A2);
                    const float2 u3 = __half22float2(A3);
                    const float2 u4 = __half22float2(A4);
                    const float2 o1 = __half22float2(ring[slot][0]);
                    const float2 o2 = __half22float2(ring[slot][1]);
                    const float2 o3 = __half22float2(ring[slot][2]);
                    const float2 o4 = __half22float2(ring[slot][3]);

                    // ---- vertical slide in fp32 (exact cancellation) ----
                    S[0] += u1.x - o1.x;  S[3] += u1.y - o1.y;
                    S[1] += u2.x - o2.x;  S[4] += u2.y - o2.y;
                    S[2] += u3.x - o3.x;  S[5] += u3.y - o3.y;
                    S[7] += u4.x - o4.x;  S[6] += u4.y - o4.y;

                    ring[slot][0] = A1;
                    ring[slot][1] = A2;
                    ring[slot][2] = A3;
                    ring[slot][3] = A4;

                    // ---- emit output row y = ybase + i - 8, i = 9a+slot ----
                    const int i = 9 * a + slot;
                    if ((a > 0 || slot >= 8) && i < ilim) {
                        const float mA = S[0] * inv_n;
                        const float mB = S[3] * inv_n;
                        const float mJ = S[6] * inv_n;
                        const float crossA = fmaf(-mA, S[6], S[2]);
                        const float varA   = fmaf(-mA, S[0], S[1]);
                        const float varJ   = fmaf(-mJ, S[6], S[7]);
                        const float crossB = fmaf(-mB, S[6], S[5]);
                        const float varB   = fmaf(-mB, S[3], S[4]);
                        const float dA = fmaf(varA, varJ, 1e-5f);
                        const float dB = fmaf(varB, varJ, 1e-5f);
                        // ccA + ccB = (crossA^2*dB + crossB^2*dA) / (dA*dB)
                        const float num = fmaf(crossB * crossB, dA,
                                               crossA * crossA * dB);
                        const float rcp = __fdividef(1.0f, dA * dB);
                        acc = fmaf(-num, rcp, acc + 2.0f);   // += 2 - (ccA+ccB)
                    }
                }
                // no bottom barrier: next iteration's first __syncthreads
                // protects both the fp32 buffer ring (depth 4) and W
            }
        }
    }

    // ---- deterministic block reduction ----
#pragma unroll
    for (int off = 16; off > 0; off >>= 1)
        acc += __shfl_xor_sync(0xffffffffu, acc, off);
    if ((tid & 31) == 0) red[tid >> 5] = acc;
    __syncthreads();

    const int bidx = (blockIdx.z * NYB + blockIdx.y) * 4 + blockIdx.x;
    if (tid == 0) {
        g_partials[bidx] = (red[0] + red[1]) + (red[2] + red[3]);
        __threadfence();
        unsigned int old = atomicInc(&g_count, NBLK - 1);  // wraps: graph-replay safe
        lastflag = (old == NBLK - 1);
    }
    __syncthreads();

    if (lastflag) {
        float v = 0.0f;
#pragma unroll
        for (int m = 0; m < NBLK / 128; ++m)     // 896 = 7 * 128
            v += g_partials[tid + 128 * m];
#pragma unroll
        for (int off = 16; off > 0; off >>= 1)
            v += __shfl_xor_sync(0xffffffffu, v, off);
        if ((tid & 31) == 0) red[tid >> 5] = v;
        __syncthreads();
        if (tid == 0) {
            const float tot = (red[0] + red[1]) + (red[2] + red[3]);
            // mean(combined) = sum(2*combined) * 0.5 / 2^23 = tot * 2^-24
            out[0] = tot * 5.9604644775390625e-08f;
        }
    }
}

extern "C" void kernel_launch(void* const* d_in, const int* in_sizes, int n_in,
                              void* d_out, int out_size)
{
    (void)in_sizes; (void)n_in; (void)out_size;
    const float* img1 = (const float*)d_in[0];
    const float* img2 = (const float*)d_in[1];
    const float* fus  = (const float*)d_in[2];

    dim3 grid(4, NYB, NB);   // 896 blocks ~= 888 concurrent slots (1.009 waves)
    ncc_fused<<<grid, 128>>>(img1, img2, fus, (float*)d_out);
}

// round 16
// speedup vs baseline: 1.3358x; 1.0057x over previous
#include <cuda_runtime.h>
#include <cuda_fp16.h>
#include <cstdint>

// NCC loss, 9x9 box, SAME zero pad, n=81 (matches reference conv).
// Round 16: R13 champion (53.8us) + decoupled conversion pipeline.
//   - W double-buffered: iteration s converts stage s+1 into W[(s+1)&1] and
//     computes taps from W[s&1] (converted last iteration). The convert->tap
//     cross-warp serialization within an iteration disappears.
//   - ONE __syncthreads per stage (was 2): the top barrier of the next
//     iteration orders conversion writes vs tap reads both ways, plus
//     cp.async visibility.
//   - wait_group 1 (stage s+1 landed at iter s); prefetch distance 2 iters.
// Kernel math byte-identical to R13: packed HFMA2 taps, fp16 ring + fp32 S
// exact-cancel slide, merged epilogue, 80-reg/6-block chassis, grid 4x8x32.
// Deterministic fused reduction (fixed-order, wrapping atomicInc).

#define WW 512
#define HH 512
#define NB 32
#define COLS 128
#define STRIPH 64
#define NBLK (4 * 8 * 32)   // 1024 blocks
#define NSTAGE 24           // 72 row-steps / 3 rows per stage
#define VECS_PER_STAGE 306  // 9 row-images * 34 float4
#define UNITS 408           // 3 rows * 136 cols per stage

__device__ float        g_partials[NBLK];
__device__ unsigned int g_count = 0;

__device__ __forceinline__ void cp16(uint32_t dst, const float* src, bool ok) {
    asm volatile("cp.async.cg.shared.global [%0], [%1], 16, %2;"
                 :: "r"(dst), "l"(src), "r"(ok ? 16 : 0) : "memory");
}
__device__ __forceinline__ void cp_commit() {
    asm volatile("cp.async.commit_group;" ::: "memory");
}
__device__ __forceinline__ void cp_wait1() {
    asm volatile("cp.async.wait_group 1;" ::: "memory");
}
__device__ __forceinline__ void cp_wait2() {
    asm volatile("cp.async.wait_group 2;" ::: "memory");
}

__global__ __launch_bounds__(128, 6)
void ncc_fused(const float* __restrict__ img1,
               const float* __restrict__ img2,
               const float* __restrict__ fus,
               float* __restrict__ out)
{
    const int tid   = threadIdx.x;
    const int xbase = blockIdx.x * COLS;
    const int ybase = blockIdx.y * STRIPH;
    const int b     = blockIdx.z;

    const size_t base = (size_t)b * (size_t)(HH * WW);
    const float* p1 = img1 + base;
    const float* p2 = img2 + base;
    const float* pf = fus  + base;

    // staged fp32: [buf][img*3+row][136]; img-major so flat u / u+408 / u+816
    __shared__ float rows[4][9][136];
    // double-buffered packed taps: uint2 {P=(a,c), G=(f,1)} per (r,x)
    __shared__ __align__(16) uint2 W2[2][UNITS];
    __shared__ float red[4];
    __shared__ int   lastflag;

    const uint32_t smem_rows = (uint32_t)__cvta_generic_to_shared(&rows[0][0][0]);

    // ---- loop-invariant staging descriptors (3 vecs per thread) ----
    const float* pb[3];
    int          joff[3];
    uint32_t     doff[3];
    bool         cokv[3];
    bool         act[3];
#pragma unroll
    for (int it = 0; it < 3; ++it) {
        const int i  = tid + 128 * it;
        act[it]      = (i < VECS_PER_STAGE);
        const int ii  = act[it] ? i : 0;
        const int ri  = ii / 34;            // row-image 0..8 = img*3 + jj
        const int vec = ii - ri * 34;
        const int img = ri / 3;
        joff[it]      = ri - img * 3;
        const int gx  = xbase - 4 + vec * 4;
        const bool ck = (gx >= 0) && (gx <= WW - 4);
        cokv[it]      = ck;
        const float* p = (img == 0) ? p1 : ((img == 1) ? p2 : pf);
        pb[it]        = p + (ck ? gx : 0);
        doff[it]      = (uint32_t)((ri * 136 + vec * 4) * 4);
    }

    auto stage = [&](int s, int buf) {
        const int r0 = ybase - 4 + 3 * s;
        const uint32_t bb = smem_rows + (uint32_t)(buf * (9 * 136 * 4));
#pragma unroll
        for (int it = 0; it < 3; ++it) {
            if (act[it]) {
                const int  r   = r0 + joff[it];
                const bool rok = ((unsigned)r < (unsigned)HH);
                const int  rc  = rok ? r : 0;
                cp16(bb + doff[it], pb[it] + (size_t)rc * WW, rok && cokv[it]);
            }
        }
    };

    // convert staged stage sc (fp32) -> packed W2[sc & 1]
    auto convertW = [&](int sc) {
        const float* Rf32 = &rows[sc & 3][0][0];
        uint2* Wd = W2[sc & 1];
#pragma unroll
        for (int it = 0; it < 4; ++it) {
            const int u = tid + 128 * it;
            if (u < UNITS) {
                const float av = Rf32[u];
                const float cv = Rf32[u + 408];
                const float fv = Rf32[u + 816];
                const __half2 P = __floats2half2_rn(av, cv);
                const __half2 G = __floats2half2_rn(fv, 1.0f);
                uint2 pk;
                pk.x = *reinterpret_cast<const unsigned*>(&P);
                pk.y = *reinterpret_cast<const unsigned*>(&G);
                Wd[u] = pk;
            }
        }
    };

    // ring stores A1..A4 (4 half2 per slot = 36 regs); S fp32
    __half2 ring[9][4];
    float S[8];
#pragma unroll
    for (int j = 0; j < 9; ++j)
#pragma unroll
        for (int q = 0; q < 4; ++q) ring[j][q] = __floats2half2_rn(0.0f, 0.0f);
#pragma unroll
    for (int q = 0; q < 8; ++q) S[q] = 0.0f;

    float acc = 0.0f;
    const float inv_n = 1.0f / 81.0f;

    stage(0, 0); cp_commit();
    stage(1, 1); cp_commit();
    stage(2, 2); cp_commit();
    cp_wait2();            // group 0 landed
    __syncthreads();
    convertW(0);           // W2[0] ready for iteration 0's taps

    for (int a = 0; a < 8; ++a) {
#pragma unroll
        for (int g = 0; g < 3; ++g) {
            const int s = 3 * a + g;
            // groups issued: 0..s+2; wait_group 1 => stage s+1 landed
            cp_wait1();
            __syncthreads();
            // this barrier orders: (a) last iter's conversion of W2[s&1] vs
            // this iter's tap reads; (b) last iter's tap reads of W2[(s+1)&1]
            // vs this iter's conversion overwrite; (c) cp.async visibility.

            if (s + 1 < NSTAGE) convertW(s + 1);
            if (s + 3 < NSTAGE) stage(s + 3, (s + 3) & 3);
            cp_commit();       // unconditional: uniform group accounting

            const uint2* Wr = W2[s & 1];

#pragma unroll
            for (int j = 0; j < 3; ++j) {
                const int slot = 3 * g + j;     // static 0..8 == (9a+slot) % 9

                // ---- packed 9-tap horizontal sums ----
                __half2 A1 = __floats2half2_rn(0.0f, 0.0f);
                __half2 A2 = A1, A3 = A1, A4 = A1;
#pragma unroll
                for (int k = 0; k < 9; ++k) {
                    const uint2 pk = Wr[j * 136 + tid + k];
                    const __half2 P = *reinterpret_cast<const __half2*>(&pk.x);
                    const __half2 G = *reinterpret_cast<const __half2*>(&pk.y);
                    const __half2 Q = __low2half2(G);   // (f,f)
                    A1 = __hadd2(A1, P);                // (Sa,  Sc)
                    A2 = __hfma2(P, P, A2);             // (Saa, Scc)
                    A3 = __hfma2(P, Q, A3);             // (Saf, Scf)
                    A4 = __hfma2(G, Q, A4);             // (Sff, Sf)
                }

                // ---- dequantize new and retiring entries (identical path) ----
                const float2 u1 = __half22float2(A1);
                const float2 u2 = __half22float2(A2);
                const float2 u3 = __half22float2(A3);
                const float2 u4 = __half22float2(A4);
                const float2 o1 = __half22float2(ring[slot][0]);
                const float2 o2 = __half22float2(ring[slot][1]);
                const float2 o3 = __half22float2(ring[slot][2]);
                const float2 o4 = __half22float2(ring[slot][3]);

                // ---- vertical slide in fp32 (exact cancellation) ----
                S[0] += u1.x - o1.x;  S[3] += u1.y - o1.y;
                S[1] += u2.x - o2.x;  S[4] += u2.y - o2.y;
                S[2] += u3.x - o3.x;  S[5] += u3.y - o3.y;
                S[7] += u4.x - o4.x;  S[6] += u4.y - o4.y;

                ring[slot][0] = A1;
                ring[slot][1] = A2;
                ring[slot][2] = A3;
                ring[slot][3] = A4;

                // ---- emit output row (row-step i = 9a+slot >= 8) ----
                if (a > 0 || slot >= 8) {
                    const float mA = S[0] * inv_n;
                    const float mB = S[3] * inv_n;
                    const float mJ = S[6] * inv_n;
                    const float crossA = fmaf(-mA, S[6], S[2]);
                    const float varA   = fmaf(-mA, S[0], S[1]);
                    const float varJ   = fmaf(-mJ, S[6], S[7]);
                    const float crossB = fmaf(-mB, S[6], S[5]);
                    const float varB   = fmaf(-mB, S[3], S[4]);
                    const float dA = fmaf(varA, varJ, 1e-5f);
                    const float dB = fmaf(varB, varJ, 1e-5f);
                    // ccA + ccB = (crossA^2*dB + crossB^2*dA) / (dA*dB)
                    const float num = fmaf(crossB * crossB, dA,
                                           crossA * crossA * dB);
                    const float rcp = __fdividef(1.0f, dA * dB);
                    acc = fmaf(-num, rcp, acc + 2.0f);   // += 2 - (ccA+ccB)
                }
            }
            // no bottom barrier: the next iteration's top __syncthreads
            // protects W2 double-buffer reuse and the fp32 rows ring (depth 4)
        }
    }

    // ---- deterministic block reduction ----
#pragma unroll
    for (int off = 16; off > 0; off >>= 1)
        acc += __shfl_xor_sync(0xffffffffu, acc, off);
    if ((tid & 31) == 0) red[tid >> 5] = acc;
    __syncthreads();

    const int bidx = (blockIdx.z * 8 + blockIdx.y) * 4 + blockIdx.x;
    if (tid == 0) {
        g_partials[bidx] = (red[0] + red[1]) + (red[2] + red[3]);
        __threadfence();
        unsigned int old = atomicInc(&g_count, NBLK - 1);  // wraps: graph-replay safe
        lastflag = (old == NBLK - 1);
    }
    __syncthreads();

    if (lastflag) {
        float v = 0.0f;
#pragma unroll
        for (int m = 0; m < NBLK / 128; ++m)
            v += g_partials[tid + 128 * m];
#pragma unroll
        for (int off = 16; off > 0; off >>= 1)
            v += __shfl_xor_sync(0xffffffffu, v, off);
        if ((tid & 31) == 0) red[tid >> 5] = v;
        __syncthreads();
        if (tid == 0) {
            const float tot = (red[0] + red[1]) + (red[2] + red[3]);
            // mean(combined) = sum(2*combined) * 0.5 / 2^23 = tot * 2^-24
            out[0] = tot * 5.9604644775390625e-08f;
        }
    }
}

extern "C" void kernel_launch(void* const* d_in, const int* in_sizes, int n_in,
                              void* d_out, int out_size)
{
    (void)in_sizes; (void)n_in; (void)out_size;
    const float* img1 = (const float*)d_in[0];
    const float* img2 = (const float*)d_in[1];
    const float* fus  = (const float*)d_in[2];

    dim3 grid(4, 8, NB);   // 1024 blocks
    ncc_fused<<<grid, 128>>>(img1, img2, fus, (float*)d_out);
}